// round 4
// baseline (speedup 1.0000x reference)
#include <cuda_runtime.h>
#include <math.h>

#define BB     8192
#define MM     200
#define EE     64
#define NOTHER 128
#define H1     96
#define WP     104    // W1eff smem stride (u32), conflict-free for B frags
#define HP     68     // hist smem stride (floats), conflict-free for A frags
#define F1     128
#define F2     85
#define F3     64

// dynamic smem layout (floats unless noted)
#define OFF_W     0                        // u32[64*104]  = 6656
#define OFF_HIST  (OFF_W + EE * WP)        // float[208*68]= 14144
#define OFF_TGT   (OFF_HIST + 208 * HP)    // 64
#define OFF_C     (OFF_TGT + 64)           // 96
#define OFF_W2    (OFF_C + 96)             // 96
#define OFF_AIJ   (OFF_W2 + 96)            // 208
#define OFF_PART  (OFF_AIJ + 208)          // 256
#define OFF_X     (OFF_PART + 256)         // 256
#define OFF_H1    (OFF_X + 256)            // 128
#define OFF_H2    (OFF_H1 + 128)           // 88
#define OFF_H3    (OFF_H2 + 88)            // 64
#define SMEM_FLOATS (OFF_H3 + 64)
#define SMEM_BYTES  (SMEM_FLOATS * 4)

__device__ __forceinline__ unsigned f2tf32(float f) {
    unsigned r;
    asm("cvt.rna.tf32.f32 %0, %1;" : "=r"(r) : "f"(f));
    return r;
}

__global__ __launch_bounds__(256, 2)
void din_kernel(const float* __restrict__ hist, const float* __restrict__ target,
                const float* __restrict__ other,
                const float* __restrict__ aW1, const float* __restrict__ ab1,
                const float* __restrict__ aW2, const float* __restrict__ ab2,
                const float* __restrict__ oW1, const float* __restrict__ ob1,
                const float* __restrict__ oW2, const float* __restrict__ ob2,
                const float* __restrict__ oW3, const float* __restrict__ ob3,
                const float* __restrict__ fW,  const float* __restrict__ fb,
                float* __restrict__ out)
{
    extern __shared__ float sm[];
    unsigned* s_W   = (unsigned*)(sm + OFF_W);
    float* s_hist = sm + OFF_HIST;
    float* s_tgt  = sm + OFF_TGT;
    float* s_c    = sm + OFF_C;
    float* s_w2   = sm + OFF_W2;
    float* s_aij  = sm + OFF_AIJ;
    float* s_part = sm + OFF_PART;
    float* s_x    = sm + OFF_X;
    float* s_h1   = sm + OFF_H1;
    float* s_h2   = sm + OFF_H2;
    float* s_h3   = sm + OFF_H3;

    const int b = blockIdx.x;
    const int t = threadIdx.x;
    const float* hb = hist + (size_t)b * MM * EE;

    if (t < EE) s_tgt[t] = target[(size_t)b * EE + t];
    if (t < H1) s_w2[t]  = aW2[t];

    // stage hist -> smem (float4, coalesced gmem)
    for (int idx = t; idx < MM * 16; idx += 256) {
        const int row = idx >> 4, q = idx & 15;
        float4 v = ((const float4*)(hb + (size_t)row * EE))[q];
        *(float4*)(s_hist + row * HP + 4 * q) = v;
    }
    // zero pad rows 200..207 (fed to MMA for the last m-tile)
    for (int idx = t; idx < 8 * HP; idx += 256)
        s_hist[200 * HP + idx] = 0.f;
    __syncthreads();

    // W1eff = W1a + diag(tgt)*W1b  (tf32 bits);  c = ab1 + tgt @ W1c
    for (int idx = t; idx < EE * H1; idx += 256) {
        const int e = idx / H1, j = idx - e * H1;
        s_W[e * WP + j] = f2tf32(aW1[idx] + s_tgt[e] * aW1[EE * H1 + idx]);
    }
    if (t < H1) {
        float acc = ab1[t];
        #pragma unroll 8
        for (int e = 0; e < EE; e++)
            acc = fmaf(s_tgt[e], aW1[(2 * EE + e) * H1 + t], acc);
        s_c[t] = acc;
    }
    __syncthreads();

    // ---- Phase 1: tf32 mma.sync, 2 m-tiles per warp sharing B fragments ----
    const int warp = t >> 5, lane = t & 31;
    const int gid = lane >> 2, tig = lane & 3;
    const float bias2 = ab2[0];

    {
        const int mt0 = warp;           // tile rows [16*mt0, 16*mt0+16)
        const int mt1 = warp + 8;       // may be >= 13 -> inactive
        const bool two = (mt1 < 13);

        // A fragments for both tiles from smem (conflict-free LDS)
        unsigned a0[8][4], a1[8][4];
        {
            const float* p00 = s_hist + (mt0 * 16 + gid) * HP + tig;
            const float* p01 = p00 + 8 * HP;
            #pragma unroll
            for (int ks = 0; ks < 8; ks++) {
                const int k0 = ks * 8;
                a0[ks][0] = f2tf32(p00[k0]);
                a0[ks][1] = f2tf32(p01[k0]);
                a0[ks][2] = f2tf32(p00[k0 + 4]);
                a0[ks][3] = f2tf32(p01[k0 + 4]);
            }
            if (two) {
                const float* p10 = s_hist + (mt1 * 16 + gid) * HP + tig;
                const float* p11 = p10 + 8 * HP;
                #pragma unroll
                for (int ks = 0; ks < 8; ks++) {
                    const int k0 = ks * 8;
                    a1[ks][0] = f2tf32(p10[k0]);
                    a1[ks][1] = f2tf32(p11[k0]);
                    a1[ks][2] = f2tf32(p10[k0 + 4]);
                    a1[ks][3] = f2tf32(p11[k0 + 4]);
                }
            }
        }

        float aij0 = 0.f, aij1 = 0.f, aij2 = 0.f, aij3 = 0.f;
        const unsigned* wbase = s_W + tig * WP + gid;

        #pragma unroll 1
        for (int nt = 0; nt < 12; nt++) {
            const int n0 = nt * 8;
            float c0 = 0.f, c1 = 0.f, c2 = 0.f, c3 = 0.f;
            float d0 = 0.f, d1 = 0.f, d2 = 0.f, d3 = 0.f;
            #pragma unroll
            for (int ks = 0; ks < 8; ks++) {
                const unsigned b0 = wbase[ks * 8 * WP + n0];
                const unsigned b1 = wbase[(ks * 8 + 4) * WP + n0];
                asm volatile(
                    "mma.sync.aligned.m16n8k8.row.col.f32.tf32.tf32.f32 "
                    "{%0,%1,%2,%3}, {%4,%5,%6,%7}, {%8,%9}, {%0,%1,%2,%3};"
                    : "+f"(c0), "+f"(c1), "+f"(c2), "+f"(c3)
                    : "r"(a0[ks][0]), "r"(a0[ks][1]), "r"(a0[ks][2]), "r"(a0[ks][3]),
                      "r"(b0), "r"(b1));
                if (two)
                    asm volatile(
                        "mma.sync.aligned.m16n8k8.row.col.f32.tf32.tf32.f32 "
                        "{%0,%1,%2,%3}, {%4,%5,%6,%7}, {%8,%9}, {%0,%1,%2,%3};"
                        : "+f"(d0), "+f"(d1), "+f"(d2), "+f"(d3)
                        : "r"(a1[ks][0]), "r"(a1[ks][1]), "r"(a1[ks][2]), "r"(a1[ks][3]),
                          "r"(b0), "r"(b1));
            }
            const int j0 = n0 + 2 * tig;
            const float cc0 = s_c[j0],  cc1 = s_c[j0 + 1];
            const float w0  = s_w2[j0], w1  = s_w2[j0 + 1];
            aij0 = fmaf(fmaxf(c0 + cc0, 0.f), w0, aij0);
            aij0 = fmaf(fmaxf(c1 + cc1, 0.f), w1, aij0);
            aij1 = fmaf(fmaxf(c2 + cc0, 0.f), w0, aij1);
            aij1 = fmaf(fmaxf(c3 + cc1, 0.f), w1, aij1);
            if (two) {
                aij2 = fmaf(fmaxf(d0 + cc0, 0.f), w0, aij2);
                aij2 = fmaf(fmaxf(d1 + cc1, 0.f), w1, aij2);
                aij3 = fmaf(fmaxf(d2 + cc0, 0.f), w0, aij3);
                aij3 = fmaf(fmaxf(d3 + cc1, 0.f), w1, aij3);
            }
        }
        aij0 += __shfl_xor_sync(0xffffffffu, aij0, 1);
        aij0 += __shfl_xor_sync(0xffffffffu, aij0, 2);
        aij1 += __shfl_xor_sync(0xffffffffu, aij1, 1);
        aij1 += __shfl_xor_sync(0xffffffffu, aij1, 2);
        aij2 += __shfl_xor_sync(0xffffffffu, aij2, 1);
        aij2 += __shfl_xor_sync(0xffffffffu, aij2, 2);
        aij3 += __shfl_xor_sync(0xffffffffu, aij3, 1);
        aij3 += __shfl_xor_sync(0xffffffffu, aij3, 2);
        if (tig == 0) {
            const int r0 = mt0 * 16 + gid;
            s_aij[r0] = aij0 + bias2;                       // r0 <= 135 < 200
            if (r0 + 8 < MM)  s_aij[r0 + 8] = aij1 + bias2;
            if (two) {
                const int r2 = mt1 * 16 + gid;
                if (r2 < MM)      s_aij[r2]     = aij2 + bias2;
                if (r2 + 8 < MM)  s_aij[r2 + 8] = aij3 + bias2;
            }
        }
    }
    __syncthreads();

    // ---- Phase 2: tmp[e] = sum_m aij[m]*hist[m][e]  (hist from smem) ----
    {
        const int chunk = t >> 6, e = t & 63;
        const int m0 = chunk * 50;
        float acc = 0.f;
        #pragma unroll 5
        for (int m = m0; m < m0 + 50; m++)
            acc = fmaf(s_aij[m], s_hist[m * HP + e], acc);
        s_part[chunk * EE + e] = acc;
    }
    __syncthreads();

    if (t < EE) {
        s_x[t]      = s_part[t] + s_part[EE + t] + s_part[2 * EE + t] + s_part[3 * EE + t];
        s_x[EE + t] = s_tgt[t];
    }
    if (t < NOTHER) s_x[2 * EE + t] = other[(size_t)b * NOTHER + t];
    __syncthreads();

    // ---- MLP head ----
    if (t < F1) {
        float acc = ob1[t];
        #pragma unroll 8
        for (int k = 0; k < 256; k++)
            acc = fmaf(s_x[k], oW1[k * F1 + t], acc);
        s_h1[t] = fmaxf(acc, 0.f);
    }
    __syncthreads();
    if (t < F2) {
        float acc = ob2[t];
        #pragma unroll 8
        for (int k = 0; k < F1; k++)
            acc = fmaf(s_h1[k], oW2[k * F2 + t], acc);
        s_h2[t] = fmaxf(acc, 0.f);
    }
    __syncthreads();
    if (t < F3) {
        float acc = ob3[t];
        #pragma unroll 5
        for (int k = 0; k < F2; k++)
            acc = fmaf(s_h2[k], oW3[k * F3 + t], acc);
        s_h3[t] = fmaxf(acc, 0.f);
    }
    __syncthreads();
    if (t < 32) {
        float v = s_h3[t] * fW[t] + s_h3[t + 32] * fW[t + 32];
        #pragma unroll
        for (int off = 16; off; off >>= 1)
            v += __shfl_xor_sync(0xffffffffu, v, off);
        if (t == 0)
            out[b] = 1.f / (1.f + expf(-(v + fb[0])));
    }
}

extern "C" void kernel_launch(void* const* d_in, const int* in_sizes, int n_in,
                              void* d_out, int out_size)
{
    const float* hist   = (const float*)d_in[0];
    const float* target = (const float*)d_in[1];
    const float* other  = (const float*)d_in[2];
    const float* aW1    = (const float*)d_in[3];
    const float* ab1    = (const float*)d_in[4];
    const float* aW2    = (const float*)d_in[5];
    const float* ab2    = (const float*)d_in[6];
    const float* oW1    = (const float*)d_in[7];
    const float* ob1    = (const float*)d_in[8];
    const float* oW2    = (const float*)d_in[9];
    const float* ob2    = (const float*)d_in[10];
    const float* oW3    = (const float*)d_in[11];
    const float* ob3    = (const float*)d_in[12];
    const float* fW     = (const float*)d_in[13];
    const float* fb     = (const float*)d_in[14];
    float* out = (float*)d_out;

    static int configured = 0;
    if (!configured) {
        cudaFuncSetAttribute(din_kernel, cudaFuncAttributeMaxDynamicSharedMemorySize,
                             SMEM_BYTES);
        configured = 1;
    }
    din_kernel<<<BB, 256, SMEM_BYTES>>>(hist, target, other, aW1, ab1, aW2, ab2,
                                        oW1, ob1, oW2, ob2, oW3, ob3, fW, fb, out);
}

// round 5
// speedup vs baseline: 1.8721x; 1.8721x over previous
#include <cuda_runtime.h>
#include <cuda_fp16.h>
#include <math.h>

#define BB     8192
#define MM     200
#define EE     64
#define NOTHER 128
#define H1     96
#define F1     128
#define F2     85
#define F3     64

// scratch for tmp (B x 64) between kernels
__device__ float g_tmp[BB * EE];

// ---------------- Kernel 1: attention + weighted sum ----------------
// dynamic smem (u32 units):
//   s_W2   [32*104]  half2 W1eff, [k2][n], stride 104    (3328 u32)
//   s_h    [208*36]  half2 hist,  [row][k2], stride 36   (7488 u32)
//   floats: tgt 64, c 96, w2 96, aij 208, part 256       (720 u32)
#define SM1_U32  (3328 + 7488 + 720)
#define SM1_BYTES (SM1_U32 * 4)

__global__ __launch_bounds__(256, 4)
void din_attn(const float* __restrict__ hist, const float* __restrict__ target,
              const float* __restrict__ aW1, const float* __restrict__ ab1,
              const float* __restrict__ aW2, const float* __restrict__ ab2)
{
    extern __shared__ unsigned sm1[];
    unsigned* s_W2 = sm1;                 // [k2*104 + n]
    unsigned* s_h  = sm1 + 3328;          // [row*36 + k2]
    float* s_tgt  = (float*)(sm1 + 3328 + 7488);
    float* s_c    = s_tgt + 64;
    float* s_w2   = s_c + 96;
    float* s_aij  = s_w2 + 96;
    float* s_part = s_aij + 208;

    const int b = blockIdx.x;
    const int t = threadIdx.x;
    const float* hb = hist + (size_t)b * MM * EE;

    if (t < EE) s_tgt[t] = target[(size_t)b * EE + t];
    if (t < H1) s_w2[t]  = aW2[t];
    __syncthreads();

    // stage hist -> smem fp16 (half2), coalesced float4 gmem reads
    for (int idx = t; idx < MM * 16; idx += 256) {
        const int row = idx >> 4, q = idx & 15;
        float4 v = ((const float4*)(hb + (size_t)row * EE))[q];
        __half2 h01 = __floats2half2_rn(v.x, v.y);
        __half2 h23 = __floats2half2_rn(v.z, v.w);
        uint2 st;
        st.x = *(unsigned*)&h01;
        st.y = *(unsigned*)&h23;
        *(uint2*)(s_h + row * 36 + 2 * q) = st;
    }
    for (int idx = t; idx < 8 * 36; idx += 256)
        s_h[200 * 36 + idx] = 0u;   // zero rows 200..207

    // W1eff = W1a + diag(tgt)*W1b, packed half2 along k;  c = ab1 + tgt@W1c
    for (int idx = t; idx < 32 * H1; idx += 256) {
        const int k2 = idx / H1, n = idx - k2 * H1;
        const int e0 = 2 * k2, e1 = 2 * k2 + 1;
        float v0 = aW1[e0 * H1 + n] + s_tgt[e0] * aW1[(EE + e0) * H1 + n];
        float v1 = aW1[e1 * H1 + n] + s_tgt[e1] * aW1[(EE + e1) * H1 + n];
        __half2 p = __floats2half2_rn(v0, v1);
        s_W2[k2 * 104 + n] = *(unsigned*)&p;
    }
    if (t < H1) {
        float acc = ab1[t];
        #pragma unroll 8
        for (int e = 0; e < EE; e++)
            acc = fmaf(s_tgt[e], aW1[(2 * EE + e) * H1 + t], acc);
        s_c[t] = acc;
    }
    __syncthreads();

    // ---- Phase 1: fp16 mma m16n8k16, one m-tile per warp, round-robin ----
    const int warp = t >> 5, lane = t & 31;
    const int gid = lane >> 2, tig = lane & 3;
    const float bias2 = ab2[0];

    for (int mt = warp; mt < 13; mt += 8) {
        // A fragments for this tile, all 4 k-steps (conflict-free LDS.32)
        unsigned A[4][4];
        const unsigned* hp = s_h + (mt * 16 + gid) * 36 + tig;
        #pragma unroll
        for (int ks = 0; ks < 4; ks++) {
            A[ks][0] = hp[8 * ks];            // row g,   k2 = 8ks+tig
            A[ks][1] = hp[288 + 8 * ks];      // row g+8
            A[ks][2] = hp[8 * ks + 4];        // row g,   k2 = 8ks+tig+4
            A[ks][3] = hp[288 + 8 * ks + 4];  // row g+8
        }

        float aij0 = 0.f, aij1 = 0.f;
        const unsigned* wb = s_W2 + tig * 104 + gid;

        #pragma unroll 1
        for (int nt = 0; nt < 12; nt++) {
            float c0 = 0.f, c1 = 0.f, c2 = 0.f, c3 = 0.f;
            #pragma unroll
            for (int ks = 0; ks < 4; ks++) {
                const unsigned b0 = wb[ks * 832 + nt * 8];        // k2 = 8ks+tig
                const unsigned b1 = wb[ks * 832 + 416 + nt * 8];  // k2 = 8ks+tig+4
                asm volatile(
                    "mma.sync.aligned.m16n8k16.row.col.f32.f16.f16.f32 "
                    "{%0,%1,%2,%3}, {%4,%5,%6,%7}, {%8,%9}, {%0,%1,%2,%3};"
                    : "+f"(c0), "+f"(c1), "+f"(c2), "+f"(c3)
                    : "r"(A[ks][0]), "r"(A[ks][1]), "r"(A[ks][2]), "r"(A[ks][3]),
                      "r"(b0), "r"(b1));
            }
            const int j0 = nt * 8 + 2 * tig;
            const float cc0 = s_c[j0],  cc1 = s_c[j0 + 1];
            const float w0  = s_w2[j0], w1  = s_w2[j0 + 1];
            aij0 = fmaf(fmaxf(c0 + cc0, 0.f), w0, aij0);
            aij0 = fmaf(fmaxf(c1 + cc1, 0.f), w1, aij0);
            aij1 = fmaf(fmaxf(c2 + cc0, 0.f), w0, aij1);
            aij1 = fmaf(fmaxf(c3 + cc1, 0.f), w1, aij1);
        }
        aij0 += __shfl_xor_sync(0xffffffffu, aij0, 1);
        aij0 += __shfl_xor_sync(0xffffffffu, aij0, 2);
        aij1 += __shfl_xor_sync(0xffffffffu, aij1, 1);
        aij1 += __shfl_xor_sync(0xffffffffu, aij1, 2);
        if (tig == 0) {
            const int r0 = mt * 16 + gid;
            if (r0 < MM)     s_aij[r0]     = aij0 + bias2;
            if (r0 + 8 < MM) s_aij[r0 + 8] = aij1 + bias2;
        }
    }
    __syncthreads();

    // ---- Phase 2: tmp[e] = sum_m aij[m]*hist[m][e]  (gmem fp32, L2-hot) ----
    {
        const int chunk = t >> 6, e = t & 63;
        const int m0 = chunk * 50;
        float acc = 0.f;
        #pragma unroll 5
        for (int m = m0; m < m0 + 50; m++)
            acc = fmaf(s_aij[m], hb[(size_t)m * EE + e], acc);
        s_part[chunk * EE + e] = acc;
    }
    __syncthreads();
    if (t < EE)
        g_tmp[(size_t)b * EE + t] =
            s_part[t] + s_part[EE + t] + s_part[2 * EE + t] + s_part[3 * EE + t];
}

// ---------------- Kernel 2: MLP head (16 batches / CTA, 128 thr) ----------------
__global__ __launch_bounds__(128)
void din_mlp(const float* __restrict__ target, const float* __restrict__ other,
             const float* __restrict__ oW1, const float* __restrict__ ob1,
             const float* __restrict__ oW2, const float* __restrict__ ob2,
             const float* __restrict__ oW3, const float* __restrict__ ob3,
             const float* __restrict__ fW,  const float* __restrict__ fb,
             float* __restrict__ out)
{
    __shared__ float s_x[16 * 260];   // x, stride 260 (bank-safe)
    __shared__ float s_h1[16 * 132];
    __shared__ float s_h2[16 * 92];

    const int t = threadIdx.x;
    const int B0 = blockIdx.x * 16;

    for (int idx = t; idx < 16 * 64; idx += 128) {
        const int bi = idx >> 6, e = idx & 63;
        s_x[bi * 260 + e]      = g_tmp[(size_t)(B0 + bi) * EE + e];
        s_x[bi * 260 + 64 + e] = target[(size_t)(B0 + bi) * EE + e];
    }
    for (int idx = t; idx < 16 * 128; idx += 128) {
        const int bi = idx >> 7, e = idx & 127;
        s_x[bi * 260 + 128 + e] = other[(size_t)(B0 + bi) * NOTHER + e];
    }
    __syncthreads();

    const int bi = t >> 3;       // 0..15
    const int jg = t & 7;        // 0..7

    // Layer 1: 256 -> 128, each thread 16 outputs
    {
        const int j0 = jg * 16;
        float acc[16];
        #pragma unroll
        for (int i = 0; i < 16; i++) acc[i] = ob1[j0 + i];
        const float* xr = s_x + bi * 260;
        #pragma unroll 4
        for (int k = 0; k < 256; k++) {
            const float xv = xr[k];
            const float4* w = (const float4*)(oW1 + k * F1 + j0);
            float4 w0 = w[0], w1 = w[1], w2 = w[2], w3 = w[3];
            acc[0]  = fmaf(xv, w0.x, acc[0]);  acc[1]  = fmaf(xv, w0.y, acc[1]);
            acc[2]  = fmaf(xv, w0.z, acc[2]);  acc[3]  = fmaf(xv, w0.w, acc[3]);
            acc[4]  = fmaf(xv, w1.x, acc[4]);  acc[5]  = fmaf(xv, w1.y, acc[5]);
            acc[6]  = fmaf(xv, w1.z, acc[6]);  acc[7]  = fmaf(xv, w1.w, acc[7]);
            acc[8]  = fmaf(xv, w2.x, acc[8]);  acc[9]  = fmaf(xv, w2.y, acc[9]);
            acc[10] = fmaf(xv, w2.z, acc[10]); acc[11] = fmaf(xv, w2.w, acc[11]);
            acc[12] = fmaf(xv, w3.x, acc[12]); acc[13] = fmaf(xv, w3.y, acc[13]);
            acc[14] = fmaf(xv, w3.z, acc[14]); acc[15] = fmaf(xv, w3.w, acc[15]);
        }
        #pragma unroll
        for (int i = 0; i < 16; i++)
            s_h1[bi * 132 + j0 + i] = fmaxf(acc[i], 0.f);
    }
    __syncthreads();

    // Layer 2: 128 -> 85, each thread up to 11 outputs
    {
        const int j0 = jg * 11;
        float acc[11];
        #pragma unroll
        for (int i = 0; i < 11; i++) acc[i] = (j0 + i < F2) ? ob2[j0 + i] : 0.f;
        const float* xr = s_h1 + bi * 132;
        #pragma unroll 2
        for (int k = 0; k < F1; k++) {
            const float xv = xr[k];
            const float* w = oW2 + k * F2;
            #pragma unroll
            for (int i = 0; i < 11; i++)
                if (j0 + i < F2) acc[i] = fmaf(xv, w[j0 + i], acc[i]);
        }
        #pragma unroll
        for (int i = 0; i < 11; i++)
            if (j0 + i < F2) s_h2[bi * 92 + j0 + i] = fmaxf(acc[i], 0.f);
    }
    __syncthreads();

    // Layer 3: 85 -> 64, each thread 8 outputs; final dot folded in
    {
        const int j0 = jg * 8;
        float acc[8];
        #pragma unroll
        for (int i = 0; i < 8; i++) acc[i] = ob3[j0 + i];
        const float* xr = s_h2 + bi * 92;
        #pragma unroll 5
        for (int k = 0; k < F2; k++) {
            const float xv = xr[k];
            const float4* w = (const float4*)(oW3 + k * F3 + j0);
            float4 w0 = w[0], w1 = w[1];
            acc[0] = fmaf(xv, w0.x, acc[0]); acc[1] = fmaf(xv, w0.y, acc[1]);
            acc[2] = fmaf(xv, w0.z, acc[2]); acc[3] = fmaf(xv, w0.w, acc[3]);
            acc[4] = fmaf(xv, w1.x, acc[4]); acc[5] = fmaf(xv, w1.y, acc[5]);
            acc[6] = fmaf(xv, w1.z, acc[6]); acc[7] = fmaf(xv, w1.w, acc[7]);
        }
        float v = 0.f;
        #pragma unroll
        for (int i = 0; i < 8; i++)
            v = fmaf(fmaxf(acc[i], 0.f), fW[j0 + i], v);
        v += __shfl_down_sync(0xffffffffu, v, 4);
        v += __shfl_down_sync(0xffffffffu, v, 2);
        v += __shfl_down_sync(0xffffffffu, v, 1);
        if (jg == 0)
            out[B0 + bi] = 1.f / (1.f + expf(-(v + fb[0])));
    }
}

extern "C" void kernel_launch(void* const* d_in, const int* in_sizes, int n_in,
                              void* d_out, int out_size)
{
    const float* hist   = (const float*)d_in[0];
    const float* target = (const float*)d_in[1];
    const float* other  = (const float*)d_in[2];
    const float* aW1    = (const float*)d_in[3];
    const float* ab1    = (const float*)d_in[4];
    const float* aW2    = (const float*)d_in[5];
    const float* ab2    = (const float*)d_in[6];
    const float* oW1    = (const float*)d_in[7];
    const float* ob1    = (const float*)d_in[8];
    const float* oW2    = (const float*)d_in[9];
    const float* ob2    = (const float*)d_in[10];
    const float* oW3    = (const float*)d_in[11];
    const float* ob3    = (const float*)d_in[12];
    const float* fW     = (const float*)d_in[13];
    const float* fb     = (const float*)d_in[14];
    float* out = (float*)d_out;

    din_attn<<<BB, 256, SM1_BYTES>>>(hist, target, aW1, ab1, aW2, ab2);
    din_mlp<<<BB / 16, 128>>>(target, other, oW1, ob1, oW2, ob2,
                              oW3, ob3, fW, fb, out);
}

// round 6
// speedup vs baseline: 2.1959x; 1.1729x over previous
#include <cuda_runtime.h>
#include <cuda_fp16.h>
#include <math.h>

#define BB     8192
#define MM     200
#define EE     64
#define NOTHER 128
#define H1     96
#define F1     128
#define F2     85
#define F3     64

__device__ float g_tmp[BB * EE];

// ---------------- Kernel 1: attention + weighted sum (unchanged from R5) ----------------
#define SM1_U32  (3328 + 7488 + 720)
#define SM1_BYTES (SM1_U32 * 4)

__global__ __launch_bounds__(256, 4)
void din_attn(const float* __restrict__ hist, const float* __restrict__ target,
              const float* __restrict__ aW1, const float* __restrict__ ab1,
              const float* __restrict__ aW2, const float* __restrict__ ab2)
{
    extern __shared__ unsigned sm1[];
    unsigned* s_W2 = sm1;                 // half2 W1eff [k2*104 + n]
    unsigned* s_h  = sm1 + 3328;          // half2 hist  [row*36 + k2]
    float* s_tgt  = (float*)(sm1 + 3328 + 7488);
    float* s_c    = s_tgt + 64;
    float* s_w2   = s_c + 96;
    float* s_aij  = s_w2 + 96;
    float* s_part = s_aij + 208;

    const int b = blockIdx.x;
    const int t = threadIdx.x;
    const float* hb = hist + (size_t)b * MM * EE;

    if (t < EE) s_tgt[t] = target[(size_t)b * EE + t];
    if (t < H1) s_w2[t]  = aW2[t];
    __syncthreads();

    for (int idx = t; idx < MM * 16; idx += 256) {
        const int row = idx >> 4, q = idx & 15;
        float4 v = ((const float4*)(hb + (size_t)row * EE))[q];
        __half2 h01 = __floats2half2_rn(v.x, v.y);
        __half2 h23 = __floats2half2_rn(v.z, v.w);
        uint2 st;
        st.x = *(unsigned*)&h01;
        st.y = *(unsigned*)&h23;
        *(uint2*)(s_h + row * 36 + 2 * q) = st;
    }
    for (int idx = t; idx < 8 * 36; idx += 256)
        s_h[200 * 36 + idx] = 0u;

    for (int idx = t; idx < 32 * H1; idx += 256) {
        const int k2 = idx / H1, n = idx - k2 * H1;
        const int e0 = 2 * k2, e1 = 2 * k2 + 1;
        float v0 = aW1[e0 * H1 + n] + s_tgt[e0] * aW1[(EE + e0) * H1 + n];
        float v1 = aW1[e1 * H1 + n] + s_tgt[e1] * aW1[(EE + e1) * H1 + n];
        __half2 p = __floats2half2_rn(v0, v1);
        s_W2[k2 * 104 + n] = *(unsigned*)&p;
    }
    if (t < H1) {
        float acc = ab1[t];
        #pragma unroll 8
        for (int e = 0; e < EE; e++)
            acc = fmaf(s_tgt[e], aW1[(2 * EE + e) * H1 + t], acc);
        s_c[t] = acc;
    }
    __syncthreads();

    const int warp = t >> 5, lane = t & 31;
    const int gid = lane >> 2, tig = lane & 3;
    const float bias2 = ab2[0];

    for (int mt = warp; mt < 13; mt += 8) {
        unsigned A[4][4];
        const unsigned* hp = s_h + (mt * 16 + gid) * 36 + tig;
        #pragma unroll
        for (int ks = 0; ks < 4; ks++) {
            A[ks][0] = hp[8 * ks];
            A[ks][1] = hp[288 + 8 * ks];
            A[ks][2] = hp[8 * ks + 4];
            A[ks][3] = hp[288 + 8 * ks + 4];
        }

        float aij0 = 0.f, aij1 = 0.f;
        const unsigned* wb = s_W2 + tig * 104 + gid;

        #pragma unroll 1
        for (int nt = 0; nt < 12; nt++) {
            float c0 = 0.f, c1 = 0.f, c2 = 0.f, c3 = 0.f;
            #pragma unroll
            for (int ks = 0; ks < 4; ks++) {
                const unsigned b0 = wb[ks * 832 + nt * 8];
                const unsigned b1 = wb[ks * 832 + 416 + nt * 8];
                asm volatile(
                    "mma.sync.aligned.m16n8k16.row.col.f32.f16.f16.f32 "
                    "{%0,%1,%2,%3}, {%4,%5,%6,%7}, {%8,%9}, {%0,%1,%2,%3};"
                    : "+f"(c0), "+f"(c1), "+f"(c2), "+f"(c3)
                    : "r"(A[ks][0]), "r"(A[ks][1]), "r"(A[ks][2]), "r"(A[ks][3]),
                      "r"(b0), "r"(b1));
            }
            const int j0 = nt * 8 + 2 * tig;
            const float cc0 = s_c[j0],  cc1 = s_c[j0 + 1];
            const float w0  = s_w2[j0], w1  = s_w2[j0 + 1];
            aij0 = fmaf(fmaxf(c0 + cc0, 0.f), w0, aij0);
            aij0 = fmaf(fmaxf(c1 + cc1, 0.f), w1, aij0);
            aij1 = fmaf(fmaxf(c2 + cc0, 0.f), w0, aij1);
            aij1 = fmaf(fmaxf(c3 + cc1, 0.f), w1, aij1);
        }
        aij0 += __shfl_xor_sync(0xffffffffu, aij0, 1);
        aij0 += __shfl_xor_sync(0xffffffffu, aij0, 2);
        aij1 += __shfl_xor_sync(0xffffffffu, aij1, 1);
        aij1 += __shfl_xor_sync(0xffffffffu, aij1, 2);
        if (tig == 0) {
            const int r0 = mt * 16 + gid;
            if (r0 < MM)     s_aij[r0]     = aij0 + bias2;
            if (r0 + 8 < MM) s_aij[r0 + 8] = aij1 + bias2;
        }
    }
    __syncthreads();

    {
        const int chunk = t >> 6, e = t & 63;
        const int m0 = chunk * 50;
        float acc = 0.f;
        #pragma unroll 5
        for (int m = m0; m < m0 + 50; m++)
            acc = fmaf(s_aij[m], hb[(size_t)m * EE + e], acc);
        s_part[chunk * EE + e] = acc;
    }
    __syncthreads();
    if (t < EE)
        g_tmp[(size_t)b * EE + t] =
            s_part[t] + s_part[EE + t] + s_part[2 * EE + t] + s_part[3 * EE + t];
}

// ---------------- Kernel 2: MLP head v2 — 1 warp : 4 batches, 32/CTA ----------------
// smem floats: s_x 32*256, s_h1 32*128, s_h2 32*88
#define MX   (32 * 256)
#define MH1  (32 * 128)
#define MH2  (32 * 88)
#define SM2_BYTES ((MX + MH1 + MH2) * 4)

__global__ __launch_bounds__(256)
void din_mlp(const float* __restrict__ target, const float* __restrict__ other,
             const float* __restrict__ oW1, const float* __restrict__ ob1,
             const float* __restrict__ oW2, const float* __restrict__ ob2,
             const float* __restrict__ oW3, const float* __restrict__ ob3,
             const float* __restrict__ fW,  const float* __restrict__ fb,
             float* __restrict__ out)
{
    extern __shared__ float sm2[];
    float* s_x  = sm2;
    float* s_h1 = sm2 + MX;
    float* s_h2 = sm2 + MX + MH1;

    const int t = threadIdx.x;
    const int B0 = blockIdx.x * 32;

    // stage x = [tmp | target | other] for 32 batches (float4, coalesced)
    for (int idx = t; idx < 512; idx += 256) {
        const int bi = idx >> 4, q = idx & 15;
        float4 v = ((const float4*)(g_tmp + (size_t)(B0 + bi) * EE))[q];
        *(float4*)(s_x + bi * 256 + 4 * q) = v;
        float4 u = ((const float4*)(target + (size_t)(B0 + bi) * EE))[q];
        *(float4*)(s_x + bi * 256 + 64 + 4 * q) = u;
    }
    for (int idx = t; idx < 1024; idx += 256) {
        const int bi = idx >> 5, q = idx & 31;
        float4 v = ((const float4*)(other + (size_t)(B0 + bi) * NOTHER))[q];
        *(float4*)(s_x + bi * 256 + 128 + 4 * q) = v;
    }
    __syncthreads();

    const int warp = t >> 5, lane = t & 31;
    const int wb = warp * 4;                 // first batch of this warp
    const float* x0 = s_x + (wb + 0) * 256;
    const float* x1 = s_x + (wb + 1) * 256;
    const float* x2 = s_x + (wb + 2) * 256;
    const float* x3 = s_x + (wb + 3) * 256;

    // ---- Layer 1: 256 -> 128 ; lane owns j = 4*lane .. 4*lane+3 ----
    {
        const int j0 = lane * 4;
        float4 b = *(const float4*)(ob1 + j0);
        float a0x = b.x, a0y = b.y, a0z = b.z, a0w = b.w;
        float a1x = b.x, a1y = b.y, a1z = b.z, a1w = b.w;
        float a2x = b.x, a2y = b.y, a2z = b.z, a2w = b.w;
        float a3x = b.x, a3y = b.y, a3z = b.z, a3w = b.w;
        #pragma unroll 4
        for (int k = 0; k < 256; k++) {
            const float4 w = *(const float4*)(oW1 + k * F1 + j0);
            const float v0 = x0[k], v1 = x1[k], v2 = x2[k], v3 = x3[k];
            a0x = fmaf(v0, w.x, a0x); a0y = fmaf(v0, w.y, a0y);
            a0z = fmaf(v0, w.z, a0z); a0w = fmaf(v0, w.w, a0w);
            a1x = fmaf(v1, w.x, a1x); a1y = fmaf(v1, w.y, a1y);
            a1z = fmaf(v1, w.z, a1z); a1w = fmaf(v1, w.w, a1w);
            a2x = fmaf(v2, w.x, a2x); a2y = fmaf(v2, w.y, a2y);
            a2z = fmaf(v2, w.z, a2z); a2w = fmaf(v2, w.w, a2w);
            a3x = fmaf(v3, w.x, a3x); a3y = fmaf(v3, w.y, a3y);
            a3z = fmaf(v3, w.z, a3z); a3w = fmaf(v3, w.w, a3w);
        }
        float4 r;
        r.x = fmaxf(a0x, 0.f); r.y = fmaxf(a0y, 0.f); r.z = fmaxf(a0z, 0.f); r.w = fmaxf(a0w, 0.f);
        *(float4*)(s_h1 + (wb + 0) * F1 + j0) = r;
        r.x = fmaxf(a1x, 0.f); r.y = fmaxf(a1y, 0.f); r.z = fmaxf(a1z, 0.f); r.w = fmaxf(a1w, 0.f);
        *(float4*)(s_h1 + (wb + 1) * F1 + j0) = r;
        r.x = fmaxf(a2x, 0.f); r.y = fmaxf(a2y, 0.f); r.z = fmaxf(a2z, 0.f); r.w = fmaxf(a2w, 0.f);
        *(float4*)(s_h1 + (wb + 2) * F1 + j0) = r;
        r.x = fmaxf(a3x, 0.f); r.y = fmaxf(a3y, 0.f); r.z = fmaxf(a3z, 0.f); r.w = fmaxf(a3w, 0.f);
        *(float4*)(s_h1 + (wb + 3) * F1 + j0) = r;
    }
    __syncwarp();

    const float* h10 = s_h1 + (wb + 0) * F1;
    const float* h11 = s_h1 + (wb + 1) * F1;
    const float* h12 = s_h1 + (wb + 2) * F1;
    const float* h13 = s_h1 + (wb + 3) * F1;

    // ---- Layer 2: 128 -> 85 ; lane owns j = 3*lane .. 3*lane+2 (guarded) ----
    {
        const int j0 = lane * 3;
        const bool g0 = (j0 < F2), g1 = (j0 + 1 < F2), g2 = (j0 + 2 < F2);
        float bb0 = g0 ? ob2[j0] : 0.f;
        float bb1 = g1 ? ob2[j0 + 1] : 0.f;
        float bb2 = g2 ? ob2[j0 + 2] : 0.f;
        float a00 = bb0, a01 = bb1, a02 = bb2;
        float a10 = bb0, a11 = bb1, a12 = bb2;
        float a20 = bb0, a21 = bb1, a22 = bb2;
        float a30 = bb0, a31 = bb1, a32 = bb2;
        #pragma unroll 4
        for (int k = 0; k < F1; k++) {
            const float* wr = oW2 + k * F2;
            const float w0 = g0 ? wr[j0] : 0.f;
            const float w1 = g1 ? wr[j0 + 1] : 0.f;
            const float w2 = g2 ? wr[j0 + 2] : 0.f;
            const float v0 = h10[k], v1 = h11[k], v2 = h12[k], v3 = h13[k];
            a00 = fmaf(v0, w0, a00); a01 = fmaf(v0, w1, a01); a02 = fmaf(v0, w2, a02);
            a10 = fmaf(v1, w0, a10); a11 = fmaf(v1, w1, a11); a12 = fmaf(v1, w2, a12);
            a20 = fmaf(v2, w0, a20); a21 = fmaf(v2, w1, a21); a22 = fmaf(v2, w2, a22);
            a30 = fmaf(v3, w0, a30); a31 = fmaf(v3, w1, a31); a32 = fmaf(v3, w2, a32);
        }
        if (g0) { s_h2[(wb+0)*88 + j0] = fmaxf(a00,0.f); s_h2[(wb+1)*88 + j0] = fmaxf(a10,0.f);
                  s_h2[(wb+2)*88 + j0] = fmaxf(a20,0.f); s_h2[(wb+3)*88 + j0] = fmaxf(a30,0.f); }
        if (g1) { s_h2[(wb+0)*88 + j0+1] = fmaxf(a01,0.f); s_h2[(wb+1)*88 + j0+1] = fmaxf(a11,0.f);
                  s_h2[(wb+2)*88 + j0+1] = fmaxf(a21,0.f); s_h2[(wb+3)*88 + j0+1] = fmaxf(a31,0.f); }
        if (g2) { s_h2[(wb+0)*88 + j0+2] = fmaxf(a02,0.f); s_h2[(wb+1)*88 + j0+2] = fmaxf(a12,0.f);
                  s_h2[(wb+2)*88 + j0+2] = fmaxf(a22,0.f); s_h2[(wb+3)*88 + j0+2] = fmaxf(a32,0.f); }
    }
    __syncwarp();

    // ---- Layer 3: 85 -> 64 ; lane owns j = lane, lane+32 ; fold final dot ----
    {
        const float b0 = ob3[lane], b1 = ob3[lane + 32];
        float a00 = b0, a01 = b1;
        float a10 = b0, a11 = b1;
        float a20 = b0, a21 = b1;
        float a30 = b0, a31 = b1;
        const float* h20 = s_h2 + (wb + 0) * 88;
        const float* h21 = s_h2 + (wb + 1) * 88;
        const float* h22 = s_h2 + (wb + 2) * 88;
        const float* h23 = s_h2 + (wb + 3) * 88;
        #pragma unroll 5
        for (int k = 0; k < F2; k++) {
            const float w0 = oW3[k * F3 + lane];
            const float w1 = oW3[k * F3 + lane + 32];
            const float v0 = h20[k], v1 = h21[k], v2 = h22[k], v3 = h23[k];
            a00 = fmaf(v0, w0, a00); a01 = fmaf(v0, w1, a01);
            a10 = fmaf(v1, w0, a10); a11 = fmaf(v1, w1, a11);
            a20 = fmaf(v2, w0, a20); a21 = fmaf(v2, w1, a21);
            a30 = fmaf(v3, w0, a30); a31 = fmaf(v3, w1, a31);
        }
        const float f0 = fW[lane], f1 = fW[lane + 32];
        float v0 = fmaxf(a00, 0.f) * f0 + fmaxf(a01, 0.f) * f1;
        float v1 = fmaxf(a10, 0.f) * f0 + fmaxf(a11, 0.f) * f1;
        float v2 = fmaxf(a20, 0.f) * f0 + fmaxf(a21, 0.f) * f1;
        float v3 = fmaxf(a30, 0.f) * f0 + fmaxf(a31, 0.f) * f1;
        #pragma unroll
        for (int off = 16; off; off >>= 1) {
            v0 += __shfl_xor_sync(0xffffffffu, v0, off);
            v1 += __shfl_xor_sync(0xffffffffu, v1, off);
            v2 += __shfl_xor_sync(0xffffffffu, v2, off);
            v3 += __shfl_xor_sync(0xffffffffu, v3, off);
        }
        if (lane == 0) {
            const float fbv = fb[0];
            out[B0 + wb + 0] = 1.f / (1.f + expf(-(v0 + fbv)));
            out[B0 + wb + 1] = 1.f / (1.f + expf(-(v1 + fbv)));
            out[B0 + wb + 2] = 1.f / (1.f + expf(-(v2 + fbv)));
            out[B0 + wb + 3] = 1.f / (1.f + expf(-(v3 + fbv)));
        }
    }
}

extern "C" void kernel_launch(void* const* d_in, const int* in_sizes, int n_in,
                              void* d_out, int out_size)
{
    const float* hist   = (const float*)d_in[0];
    const float* target = (const float*)d_in[1];
    const float* other  = (const float*)d_in[2];
    const float* aW1    = (const float*)d_in[3];
    const float* ab1    = (const float*)d_in[4];
    const float* aW2    = (const float*)d_in[5];
    const float* ab2    = (const float*)d_in[6];
    const float* oW1    = (const float*)d_in[7];
    const float* ob1    = (const float*)d_in[8];
    const float* oW2    = (const float*)d_in[9];
    const float* ob2    = (const float*)d_in[10];
    const float* oW3    = (const float*)d_in[11];
    const float* ob3    = (const float*)d_in[12];
    const float* fW     = (const float*)d_in[13];
    const float* fb     = (const float*)d_in[14];
    float* out = (float*)d_out;

    static int configured = 0;
    if (!configured) {
        cudaFuncSetAttribute(din_mlp, cudaFuncAttributeMaxDynamicSharedMemorySize,
                             SM2_BYTES);
        configured = 1;
    }
    din_attn<<<BB, 256, SM1_BYTES>>>(hist, target, aW1, ab1, aW2, ab2);
    din_mlp<<<BB / 32, 256, SM2_BYTES>>>(target, other, oW1, ob1, oW2, ob2,
                                         oW3, ob3, fW, fb, out);
}

// round 7
// speedup vs baseline: 2.3100x; 1.0520x over previous
#include <cuda_runtime.h>
#include <cuda_fp16.h>
#include <math.h>

#define BB     8192
#define MM     200
#define EE     64
#define NOTHER 128
#define H1     96
#define F1     128
#define F2     85
#define F3     64

__device__ float g_tmp[BB * EE];

// ---------------- Kernel 1: attention + weighted sum (unchanged from R5/R6) ----------------
#define SM1_U32  (3328 + 7488 + 720)
#define SM1_BYTES (SM1_U32 * 4)

__global__ __launch_bounds__(256, 4)
void din_attn(const float* __restrict__ hist, const float* __restrict__ target,
              const float* __restrict__ aW1, const float* __restrict__ ab1,
              const float* __restrict__ aW2, const float* __restrict__ ab2)
{
    extern __shared__ unsigned sm1[];
    unsigned* s_W2 = sm1;                 // half2 W1eff [k2*104 + n]
    unsigned* s_h  = sm1 + 3328;          // half2 hist  [row*36 + k2]
    float* s_tgt  = (float*)(sm1 + 3328 + 7488);
    float* s_c    = s_tgt + 64;
    float* s_w2   = s_c + 96;
    float* s_aij  = s_w2 + 96;
    float* s_part = s_aij + 208;

    const int b = blockIdx.x;
    const int t = threadIdx.x;
    const float* hb = hist + (size_t)b * MM * EE;

    if (t < EE) s_tgt[t] = target[(size_t)b * EE + t];
    if (t < H1) s_w2[t]  = aW2[t];
    __syncthreads();

    for (int idx = t; idx < MM * 16; idx += 256) {
        const int row = idx >> 4, q = idx & 15;
        float4 v = ((const float4*)(hb + (size_t)row * EE))[q];
        __half2 h01 = __floats2half2_rn(v.x, v.y);
        __half2 h23 = __floats2half2_rn(v.z, v.w);
        uint2 st;
        st.x = *(unsigned*)&h01;
        st.y = *(unsigned*)&h23;
        *(uint2*)(s_h + row * 36 + 2 * q) = st;
    }
    for (int idx = t; idx < 8 * 36; idx += 256)
        s_h[200 * 36 + idx] = 0u;

    for (int idx = t; idx < 32 * H1; idx += 256) {
        const int k2 = idx / H1, n = idx - k2 * H1;
        const int e0 = 2 * k2, e1 = 2 * k2 + 1;
        float v0 = aW1[e0 * H1 + n] + s_tgt[e0] * aW1[(EE + e0) * H1 + n];
        float v1 = aW1[e1 * H1 + n] + s_tgt[e1] * aW1[(EE + e1) * H1 + n];
        __half2 p = __floats2half2_rn(v0, v1);
        s_W2[k2 * 104 + n] = *(unsigned*)&p;
    }
    if (t < H1) {
        float acc = ab1[t];
        #pragma unroll 8
        for (int e = 0; e < EE; e++)
            acc = fmaf(s_tgt[e], aW1[(2 * EE + e) * H1 + t], acc);
        s_c[t] = acc;
    }
    __syncthreads();

    const int warp = t >> 5, lane = t & 31;
    const int gid = lane >> 2, tig = lane & 3;
    const float bias2 = ab2[0];

    for (int mt = warp; mt < 13; mt += 8) {
        unsigned A[4][4];
        const unsigned* hp = s_h + (mt * 16 + gid) * 36 + tig;
        #pragma unroll
        for (int ks = 0; ks < 4; ks++) {
            A[ks][0] = hp[8 * ks];
            A[ks][1] = hp[288 + 8 * ks];
            A[ks][2] = hp[8 * ks + 4];
            A[ks][3] = hp[288 + 8 * ks + 4];
        }

        float aij0 = 0.f, aij1 = 0.f;
        const unsigned* wb = s_W2 + tig * 104 + gid;

        #pragma unroll 1
        for (int nt = 0; nt < 12; nt++) {
            float c0 = 0.f, c1 = 0.f, c2 = 0.f, c3 = 0.f;
            #pragma unroll
            for (int ks = 0; ks < 4; ks++) {
                const unsigned b0 = wb[ks * 832 + nt * 8];
                const unsigned b1 = wb[ks * 832 + 416 + nt * 8];
                asm volatile(
                    "mma.sync.aligned.m16n8k16.row.col.f32.f16.f16.f32 "
                    "{%0,%1,%2,%3}, {%4,%5,%6,%7}, {%8,%9}, {%0,%1,%2,%3};"
                    : "+f"(c0), "+f"(c1), "+f"(c2), "+f"(c3)
                    : "r"(A[ks][0]), "r"(A[ks][1]), "r"(A[ks][2]), "r"(A[ks][3]),
                      "r"(b0), "r"(b1));
            }
            const int j0 = nt * 8 + 2 * tig;
            const float cc0 = s_c[j0],  cc1 = s_c[j0 + 1];
            const float w0  = s_w2[j0], w1  = s_w2[j0 + 1];
            aij0 = fmaf(fmaxf(c0 + cc0, 0.f), w0, aij0);
            aij0 = fmaf(fmaxf(c1 + cc1, 0.f), w1, aij0);
            aij1 = fmaf(fmaxf(c2 + cc0, 0.f), w0, aij1);
            aij1 = fmaf(fmaxf(c3 + cc1, 0.f), w1, aij1);
        }
        aij0 += __shfl_xor_sync(0xffffffffu, aij0, 1);
        aij0 += __shfl_xor_sync(0xffffffffu, aij0, 2);
        aij1 += __shfl_xor_sync(0xffffffffu, aij1, 1);
        aij1 += __shfl_xor_sync(0xffffffffu, aij1, 2);
        if (tig == 0) {
            const int r0 = mt * 16 + gid;
            if (r0 < MM)     s_aij[r0]     = aij0 + bias2;
            if (r0 + 8 < MM) s_aij[r0 + 8] = aij1 + bias2;
        }
    }
    __syncthreads();

    {
        const int chunk = t >> 6, e = t & 63;
        const int m0 = chunk * 50;
        float acc = 0.f;
        #pragma unroll 5
        for (int m = m0; m < m0 + 50; m++)
            acc = fmaf(s_aij[m], hb[(size_t)m * EE + e], acc);
        s_part[chunk * EE + e] = acc;
    }
    __syncthreads();
    if (t < EE)
        g_tmp[(size_t)b * EE + t] =
            s_part[t] + s_part[EE + t] + s_part[2 * EE + t] + s_part[3 * EE + t];
}

// ---------------- Kernel 2: MLP v3 — 2 batches/warp, 16 batches/CTA, grid 512 ----------------
#define NB   16
#define MX   (NB * 256)
#define MH1  (NB * F1)
#define MH2  (NB * 88)
#define SM2_BYTES ((MX + MH1 + MH2) * 4)

__global__ __launch_bounds__(256)
void din_mlp(const float* __restrict__ target, const float* __restrict__ other,
             const float* __restrict__ oW1, const float* __restrict__ ob1,
             const float* __restrict__ oW2, const float* __restrict__ ob2,
             const float* __restrict__ oW3, const float* __restrict__ ob3,
             const float* __restrict__ fW,  const float* __restrict__ fb,
             float* __restrict__ out)
{
    extern __shared__ float sm2[];
    float* s_x  = sm2;
    float* s_h1 = sm2 + MX;
    float* s_h2 = sm2 + MX + MH1;

    const int t = threadIdx.x;
    const int B0 = blockIdx.x * NB;

    // stage x = [tmp | target | other] for NB batches (float4, coalesced)
    for (int idx = t; idx < NB * 16; idx += 256) {
        const int bi = idx >> 4, q = idx & 15;
        float4 v = ((const float4*)(g_tmp + (size_t)(B0 + bi) * EE))[q];
        *(float4*)(s_x + bi * 256 + 4 * q) = v;
        float4 u = ((const float4*)(target + (size_t)(B0 + bi) * EE))[q];
        *(float4*)(s_x + bi * 256 + 64 + 4 * q) = u;
    }
    for (int idx = t; idx < NB * 32; idx += 256) {
        const int bi = idx >> 5, q = idx & 31;
        float4 v = ((const float4*)(other + (size_t)(B0 + bi) * NOTHER))[q];
        *(float4*)(s_x + bi * 256 + 128 + 4 * q) = v;
    }
    __syncthreads();

    const int warp = t >> 5, lane = t & 31;
    const int wb = warp * 2;                 // 2 batches per warp
    const float* x0 = s_x + (wb + 0) * 256;
    const float* x1 = s_x + (wb + 1) * 256;

    // ---- Layer 1: 256 -> 128 ; lane owns j = 4*lane..+3 (float4) ----
    {
        const int j0 = lane * 4;
        float4 bv = *(const float4*)(ob1 + j0);
        float a0x = bv.x, a0y = bv.y, a0z = bv.z, a0w = bv.w;
        float a1x = bv.x, a1y = bv.y, a1z = bv.z, a1w = bv.w;
        #pragma unroll 4
        for (int k = 0; k < 256; k += 4) {
            const float4 v0 = *(const float4*)(x0 + k);
            const float4 v1 = *(const float4*)(x1 + k);
            #pragma unroll
            for (int i = 0; i < 4; i++) {
                const float4 w = *(const float4*)(oW1 + (k + i) * F1 + j0);
                const float e0 = (i == 0) ? v0.x : (i == 1) ? v0.y : (i == 2) ? v0.z : v0.w;
                const float e1 = (i == 0) ? v1.x : (i == 1) ? v1.y : (i == 2) ? v1.z : v1.w;
                a0x = fmaf(e0, w.x, a0x); a0y = fmaf(e0, w.y, a0y);
                a0z = fmaf(e0, w.z, a0z); a0w = fmaf(e0, w.w, a0w);
                a1x = fmaf(e1, w.x, a1x); a1y = fmaf(e1, w.y, a1y);
                a1z = fmaf(e1, w.z, a1z); a1w = fmaf(e1, w.w, a1w);
            }
        }
        float4 r;
        r.x = fmaxf(a0x, 0.f); r.y = fmaxf(a0y, 0.f); r.z = fmaxf(a0z, 0.f); r.w = fmaxf(a0w, 0.f);
        *(float4*)(s_h1 + (wb + 0) * F1 + j0) = r;
        r.x = fmaxf(a1x, 0.f); r.y = fmaxf(a1y, 0.f); r.z = fmaxf(a1z, 0.f); r.w = fmaxf(a1w, 0.f);
        *(float4*)(s_h1 + (wb + 1) * F1 + j0) = r;
    }
    __syncwarp();

    const float* h10 = s_h1 + (wb + 0) * F1;
    const float* h11 = s_h1 + (wb + 1) * F1;

    // ---- Layer 2: 128 -> 85 ; lane owns j = lane, lane+32, lane+64 (coalesced) ----
    {
        const int j2 = lane + 64;
        const bool g2 = (j2 < F2);
        float b0 = ob2[lane], b1 = ob2[lane + 32], b2 = g2 ? ob2[j2] : 0.f;
        float a00 = b0, a01 = b1, a02 = b2;
        float a10 = b0, a11 = b1, a12 = b2;
        #pragma unroll 4
        for (int k = 0; k < F1; k += 4) {
            const float4 v0 = *(const float4*)(h10 + k);
            const float4 v1 = *(const float4*)(h11 + k);
            #pragma unroll
            for (int i = 0; i < 4; i++) {
                const float* wr = oW2 + (k + i) * F2;
                const float w0 = wr[lane];
                const float w1 = wr[lane + 32];
                const float w2 = g2 ? wr[j2] : 0.f;
                const float e0 = (i == 0) ? v0.x : (i == 1) ? v0.y : (i == 2) ? v0.z : v0.w;
                const float e1 = (i == 0) ? v1.x : (i == 1) ? v1.y : (i == 2) ? v1.z : v1.w;
                a00 = fmaf(e0, w0, a00); a01 = fmaf(e0, w1, a01); a02 = fmaf(e0, w2, a02);
                a10 = fmaf(e1, w0, a10); a11 = fmaf(e1, w1, a11); a12 = fmaf(e1, w2, a12);
            }
        }
        s_h2[(wb + 0) * 88 + lane]      = fmaxf(a00, 0.f);
        s_h2[(wb + 0) * 88 + lane + 32] = fmaxf(a01, 0.f);
        s_h2[(wb + 1) * 88 + lane]      = fmaxf(a10, 0.f);
        s_h2[(wb + 1) * 88 + lane + 32] = fmaxf(a11, 0.f);
        if (g2) {
            s_h2[(wb + 0) * 88 + j2] = fmaxf(a02, 0.f);
            s_h2[(wb + 1) * 88 + j2] = fmaxf(a12, 0.f);
        }
    }
    __syncwarp();

    // ---- Layer 3: 85 -> 64 ; lane owns j = lane, lane+32 ; fold final dot ----
    {
        const float b0 = ob3[lane], b1 = ob3[lane + 32];
        float a00 = b0, a01 = b1;
        float a10 = b0, a11 = b1;
        const float* h20 = s_h2 + (wb + 0) * 88;
        const float* h21 = s_h2 + (wb + 1) * 88;
        #pragma unroll 5
        for (int k = 0; k < F2; k++) {
            const float w0 = oW3[k * F3 + lane];
            const float w1 = oW3[k * F3 + lane + 32];
            const float v0 = h20[k], v1 = h21[k];
            a00 = fmaf(v0, w0, a00); a01 = fmaf(v0, w1, a01);
            a10 = fmaf(v1, w0, a10); a11 = fmaf(v1, w1, a11);
        }
        const float f0 = fW[lane], f1 = fW[lane + 32];
        float v0 = fmaxf(a00, 0.f) * f0 + fmaxf(a01, 0.f) * f1;
        float v1 = fmaxf(a10, 0.f) * f0 + fmaxf(a11, 0.f) * f1;
        #pragma unroll
        for (int off = 16; off; off >>= 1) {
            v0 += __shfl_xor_sync(0xffffffffu, v0, off);
            v1 += __shfl_xor_sync(0xffffffffu, v1, off);
        }
        if (lane == 0) {
            const float fbv = fb[0];
            out[B0 + wb + 0] = 1.f / (1.f + expf(-(v0 + fbv)));
            out[B0 + wb + 1] = 1.f / (1.f + expf(-(v1 + fbv)));
        }
    }
}

extern "C" void kernel_launch(void* const* d_in, const int* in_sizes, int n_in,
                              void* d_out, int out_size)
{
    const float* hist   = (const float*)d_in[0];
    const float* target = (const float*)d_in[1];
    const float* other  = (const float*)d_in[2];
    const float* aW1    = (const float*)d_in[3];
    const float* ab1    = (const float*)d_in[4];
    const float* aW2    = (const float*)d_in[5];
    const float* ab2    = (const float*)d_in[6];
    const float* oW1    = (const float*)d_in[7];
    const float* ob1    = (const float*)d_in[8];
    const float* oW2    = (const float*)d_in[9];
    const float* ob2    = (const float*)d_in[10];
    const float* oW3    = (const float*)d_in[11];
    const float* ob3    = (const float*)d_in[12];
    const float* fW     = (const float*)d_in[13];
    const float* fb     = (const float*)d_in[14];
    float* out = (float*)d_out;

    static int configured = 0;
    if (!configured) {
        cudaFuncSetAttribute(din_mlp, cudaFuncAttributeMaxDynamicSharedMemorySize,
                             SM2_BYTES);
        configured = 1;
    }
    din_attn<<<BB, 256, SM1_BYTES>>>(hist, target, aW1, ab1, aW2, ab2);
    din_mlp<<<BB / NB, 256, SM2_BYTES>>>(target, other, oW1, ob1, oW2, ob2,
                                         oW3, ob3, fW, fb, out);
}